// round 4
// baseline (speedup 1.0000x reference)
#include <cuda_runtime.h>
#include <cuda_bf16.h>
#include <cstdint>

// ---------------- problem constants ----------------
#define BATCH 256
#define LSEQ  256
#define CNODE 128
#define HID   128
#define NHEAD 4
#define DHEAD 32
#define NEDGE 4096
#define NSLOT (NEDGE + CNODE)               // 4224 incl. self loops
#define NNODE (BATCH * CNODE)               // 32768
#define OUT_ELEMS  (BATCH * LSEQ * CNODE)   // 8388608
#define ATTN_ELEMS (BATCH * CNODE * CNODE)  // 4194304

// ---------------- scratch ----------------
__device__ float g_h[NNODE * HID];         // 16 MB  node features
__device__ float g_xl[NNODE * HID];        // 16 MB
__device__ float g_xr[NNODE * HID];        // 16 MB
__device__ int   g_slot_ptr[CNODE + 1];    // slot CSR (self-loop first per dst)
__device__ int   g_slot_src[NSLOT];

// packed f32x2 FMA (ptxas never auto-fuses; must come from PTX)
#define FMA2(d, a, b, c) \
    asm("fma.rn.f32x2 %0, %1, %2, %3;" : "=l"(d) : "l"(a), "l"(b), "l"(c))

// ---------------- CSR/slot build ----------------
__global__ void build_csr_kernel(const void* __restrict__ eiraw) {
    __shared__ int cnt[CNODE];
    __shared__ int base[CNODE + 1];
    __shared__ int is64_s;
    const long long* e64 = (const long long*)eiraw;
    const int* e32 = (const int*)eiraw;
    int tid = threadIdx.x;

    if (tid == 0) is64_s = 1;
    if (tid < CNODE) cnt[tid] = 0;
    __syncthreads();
    int bad = 0;
    for (int i = tid; i < NEDGE; i += 256) {
        long long v = e64[i];
        if (v < 0 || v >= CNODE) bad = 1;
    }
    if (bad) is64_s = 0;
    __syncthreads();
    const int is64 = is64_s;

    for (int e = tid; e < NEDGE; e += 256) {
        int d = is64 ? (int)e64[NEDGE + e] : e32[NEDGE + e];
        atomicAdd(&cnt[d], 1);
    }
    __syncthreads();
    if (tid == 0) {
        int run = 0;
        for (int i = 0; i < CNODE; ++i) { base[i] = run; run += cnt[i]; }
        base[CNODE] = run;
    }
    __syncthreads();
    if (tid <= CNODE) g_slot_ptr[tid] = base[tid] + tid;
    if (tid < CNODE) {
        g_slot_src[base[tid] + tid] = tid;   // self loop first
        cnt[tid] = base[tid];
    }
    __syncthreads();
    for (int e = tid; e < NEDGE; e += 256) {
        int d = is64 ? (int)e64[NEDGE + e] : e32[NEDGE + e];
        int s = is64 ? (int)e64[e]         : e32[e];
        int pos = atomicAdd(&cnt[d], 1);
        g_slot_src[pos + d + 1] = s;
    }
}

// ---------------- fused GEMM ----------------
// C(MxN-tile 64x128) = A(MxK) @ W(KxN) + bias, double-buffered, f32x2 dual-k acc.
// mode 0: A row-major (lda), C row-major (ldc)
// mode 1: A = x tensor (B,L,C); A[m][k] = x[m>>7][k][m&127]  (fused input transpose)
// mode 2: C = out tensor (B,L,C); out[m0>>7][n0+l][(m0&127)+c] = C[c][l] (fused out transpose)
#define AST 36                      // A_s row stride (floats)
__global__ __launch_bounds__(256, 2) void gemm_kernel(
    const float* __restrict__ A, int lda,
    const float* __restrict__ W, int ldb,
    const float* __restrict__ bias,
    float* __restrict__ C, int ldc, int K, int mode)
{
    __shared__ __align__(16) float smem_all[12800];   // 50 KB
    float* const As0 = smem_all;
    float* const As1 = smem_all + 2304;
    float* const Bs0 = smem_all + 4608;               // pair-major f32x2: [16kp][128n][2]
    float* const Bs1 = smem_all + 8704;

    const int tid = threadIdx.x;
    const int tx = tid & 31, ty = tid >> 5;
    const int m0 = blockIdx.y * 64;
    const int n0 = blockIdx.x * 128;

    unsigned long long acc[8][4];
    #pragma unroll
    for (int i = 0; i < 8; ++i)
        #pragma unroll
        for (int j = 0; j < 4; ++j) acc[i][j] = 0ull;

    float4 aR[2], bR[4];
    const int nc = K >> 5;

    // ---- LDG chunk 0 ----
    {
        const int k0 = 0;
        if (mode == 1) {
            const float* xb = A + (size_t)(m0 >> 7) * (LSEQ * CNODE) + (m0 & 127);
            #pragma unroll
            for (int r = 0; r < 2; ++r) {
                int f4 = tid + r * 256;
                int kk = f4 >> 4, mq = f4 & 15;
                aR[r] = *(const float4*)(xb + (size_t)(k0 + kk) * CNODE + mq * 4);
            }
        } else {
            #pragma unroll
            for (int r = 0; r < 2; ++r) {
                int f4 = tid + r * 256;
                int m = f4 >> 3, kq = f4 & 7;
                aR[r] = *(const float4*)(A + (size_t)(m0 + m) * lda + k0 + kq * 4);
            }
        }
        #pragma unroll
        for (int r = 0; r < 4; ++r) {
            int f4 = tid + r * 256;
            int kk = f4 >> 5, nq = f4 & 31;
            bR[r] = *(const float4*)(W + (size_t)(k0 + kk) * ldb + n0 + nq * 4);
        }
    }

    for (int c = 0; c < nc; ++c) {
        float* Ab = (c & 1) ? As1 : As0;
        float* Bb = (c & 1) ? Bs1 : Bs0;
        // ---- STS current chunk ----
        if (mode == 1) {
            #pragma unroll
            for (int r = 0; r < 2; ++r) {
                int f4 = tid + r * 256;
                int kk = f4 >> 4, mq = f4 & 15;
                float* p = Ab + kk;
                p[(mq * 4 + 0) * AST] = aR[r].x;
                p[(mq * 4 + 1) * AST] = aR[r].y;
                p[(mq * 4 + 2) * AST] = aR[r].z;
                p[(mq * 4 + 3) * AST] = aR[r].w;
            }
        } else {
            #pragma unroll
            for (int r = 0; r < 2; ++r) {
                int f4 = tid + r * 256;
                int m = f4 >> 3, kq = f4 & 7;
                *(float4*)(Ab + m * AST + kq * 4) = aR[r];
            }
        }
        #pragma unroll
        for (int r = 0; r < 4; ++r) {
            int f4 = tid + r * 256;
            int kk = f4 >> 5, nq = f4 & 31;
            float* p = Bb + (kk >> 1) * 256 + (kk & 1);
            p[(nq * 4 + 0) * 2] = bR[r].x;
            p[(nq * 4 + 1) * 2] = bR[r].y;
            p[(nq * 4 + 2) * 2] = bR[r].z;
            p[(nq * 4 + 3) * 2] = bR[r].w;
        }
        __syncthreads();
        // ---- LDG next chunk (overlaps with compute) ----
        if (c + 1 < nc) {
            const int k0 = (c + 1) << 5;
            if (mode == 1) {
                const float* xb = A + (size_t)(m0 >> 7) * (LSEQ * CNODE) + (m0 & 127);
                #pragma unroll
                for (int r = 0; r < 2; ++r) {
                    int f4 = tid + r * 256;
                    int kk = f4 >> 4, mq = f4 & 15;
                    aR[r] = *(const float4*)(xb + (size_t)(k0 + kk) * CNODE + mq * 4);
                }
            } else {
                #pragma unroll
                for (int r = 0; r < 2; ++r) {
                    int f4 = tid + r * 256;
                    int m = f4 >> 3, kq = f4 & 7;
                    aR[r] = *(const float4*)(A + (size_t)(m0 + m) * lda + k0 + kq * 4);
                }
            }
            #pragma unroll
            for (int r = 0; r < 4; ++r) {
                int f4 = tid + r * 256;
                int kk = f4 >> 5, nq = f4 & 31;
                bR[r] = *(const float4*)(W + (size_t)(k0 + kk) * ldb + n0 + nq * 4);
            }
        }
        // ---- compute ----
        #pragma unroll
        for (int kp = 0; kp < 16; ++kp) {
            unsigned long long b2[4];
            #pragma unroll
            for (int j = 0; j < 4; ++j)
                b2[j] = *(const unsigned long long*)(Bb + kp * 256 + (tx + j * 32) * 2);
            #pragma unroll
            for (int i = 0; i < 8; ++i) {
                unsigned long long a2 = *(const unsigned long long*)(Ab + (ty * 8 + i) * AST + kp * 2);
                #pragma unroll
                for (int j = 0; j < 4; ++j)
                    FMA2(acc[i][j], a2, b2[j], acc[i][j]);
            }
        }
    }

    if (mode != 2) {
        #pragma unroll
        for (int i = 0; i < 8; ++i) {
            int m = m0 + ty * 8 + i;
            #pragma unroll
            for (int j = 0; j < 4; ++j) {
                int n = n0 + tx + j * 32;
                float2 p = *(float2*)&acc[i][j];
                C[(size_t)m * ldc + n] = p.x + p.y + bias[n];
            }
        }
    } else {
        __syncthreads();                              // everyone done reading smem
        float* Cs = smem_all;                         // [64 c][128 l] stride 129
        #pragma unroll
        for (int i = 0; i < 8; ++i) {
            #pragma unroll
            for (int j = 0; j < 4; ++j) {
                int n = tx + j * 32;
                float2 p = *(float2*)&acc[i][j];
                Cs[(ty * 8 + i) * 129 + n] = p.x + p.y + bias[n0 + n];
            }
        }
        __syncthreads();
        const int b = m0 >> 7, c0 = m0 & 127;
        float* ob = C + (size_t)b * (LSEQ * CNODE) + c0;
        #pragma unroll
        for (int rep = 0; rep < 8; ++rep) {
            int l = rep * 16 + (tid >> 4);
            int ci = (tid & 15) * 4;
            float4 v;
            v.x = Cs[(ci + 0) * 129 + l];
            v.y = Cs[(ci + 1) * 129 + l];
            v.z = Cs[(ci + 2) * 129 + l];
            v.w = Cs[(ci + 3) * 129 + l];
            *(float4*)(ob + (size_t)(n0 + l) * CNODE + ci) = v;
        }
    }
}

// ---------------- GAT layer kernel (warp-per-dst, all warp-local) ----------------
#define XL_F     (CNODE * 132)                 // 16896
#define LBUF_F   (16 * 128 * 4)                // 8192
#define ATTN_F   (16 * 128)                    // 2048
#define A_F      128
#define SMEM_F   (XL_F + LBUF_F + ATTN_F + A_F)
#define SRC_B_OFF (SMEM_F * 4)
#define PTR_B_OFF (SRC_B_OFF + NSLOT)
#define GAT_SMEM_BYTES (PTR_B_OFF + (CNODE + 1) * 4)

__global__ __launch_bounds__(512, 2) void gat_kernel(
    float* __restrict__ h, const float* __restrict__ xl, const float* __restrict__ xr,
    const float* __restrict__ att, const float* __restrict__ gat_bias,
    const float* __restrict__ ln_g, const float* __restrict__ ln_b,
    float* __restrict__ attn_out)
{
    extern __shared__ __align__(16) float sm[];
    float* xl_s   = sm;
    float* lbuf   = sm + XL_F;
    float* attnrow= sm + XL_F + LBUF_F;
    float* a_s    = sm + XL_F + LBUF_F + ATTN_F;
    unsigned char* src8 = (unsigned char*)sm + SRC_B_OFF;
    int* ptr_s = (int*)((char*)sm + PTR_B_OFF);

    const int b = blockIdx.x;
    const int tid = threadIdx.x;
    const int w = tid >> 5;
    const int l = tid & 31;
    const int hh = l >> 3;

    {
        const float4* src4 = (const float4*)(xl + (size_t)b * CNODE * HID);
        for (int i = tid; i < CNODE * 32; i += 512) {
            int node = i >> 5, d4 = i & 31;
            ((float4*)xl_s)[node * 33 + d4] = src4[i];
        }
        for (int i = tid; i < NSLOT; i += 512) src8[i] = (unsigned char)g_slot_src[i];
        if (tid <= CNODE) ptr_s[tid] = g_slot_ptr[tid];
        if (tid < 128) a_s[tid] = att[tid];
    }
    __syncthreads();

    const float4 a4 = ((const float4*)a_s)[l];
    const float4 bias4 = ((const float4*)gat_bias)[l];
    const float4 g4v = ((const float4*)ln_g)[l];
    const float4 b4v = ((const float4*)ln_b)[l];
    float* mybuf = lbuf + w * 512;
    const float4* xls4 = (const float4*)xl_s;

    for (int d = w; d < CNODE; d += 16) {
        const int sb = ptr_s[d];
        int E1 = ptr_s[d + 1] - sb;
        if (E1 > 128) E1 = 128;
        const size_t node = (size_t)b * CNODE + d;
        const float4 xr4 = ((const float4*)(xr + node * HID))[l];

        float m = -1e30f;
        #pragma unroll 2
        for (int k = 0; k < E1; ++k) {
            const int src = src8[sb + k];
            const float4 v = xls4[src * 33 + l];
            float p;
            {
                float t0 = v.x + xr4.x; t0 = fmaxf(t0, 0.2f * t0);
                float t1 = v.y + xr4.y; t1 = fmaxf(t1, 0.2f * t1);
                float t2 = v.z + xr4.z; t2 = fmaxf(t2, 0.2f * t2);
                float t3 = v.w + xr4.w; t3 = fmaxf(t3, 0.2f * t3);
                p = t0 * a4.x + t1 * a4.y + t2 * a4.z + t3 * a4.w;
            }
            p += __shfl_xor_sync(0xffffffffu, p, 4);
            p += __shfl_xor_sync(0xffffffffu, p, 2);
            p += __shfl_xor_sync(0xffffffffu, p, 1);
            if ((l & 7) == 0) mybuf[k * 4 + hh] = p;
            m = fmaxf(m, p);
        }
        __syncwarp();
        float4 m4;
        m4.x = __shfl_sync(0xffffffffu, m, 0);
        m4.y = __shfl_sync(0xffffffffu, m, 8);
        m4.z = __shfl_sync(0xffffffffu, m, 16);
        m4.w = __shfl_sync(0xffffffffu, m, 24);

        float4 s4 = {0.f, 0.f, 0.f, 0.f};
        for (int k = l; k < E1; k += 32) {
            float4 f = ((float4*)mybuf)[k];
            f.x = __expf(f.x - m4.x);
            f.y = __expf(f.y - m4.y);
            f.z = __expf(f.z - m4.z);
            f.w = __expf(f.w - m4.w);
            ((float4*)mybuf)[k] = f;
            s4.x += f.x; s4.y += f.y; s4.z += f.z; s4.w += f.w;
        }
        #pragma unroll
        for (int o = 16; o; o >>= 1) {
            s4.x += __shfl_xor_sync(0xffffffffu, s4.x, o);
            s4.y += __shfl_xor_sync(0xffffffffu, s4.y, o);
            s4.z += __shfl_xor_sync(0xffffffffu, s4.z, o);
            s4.w += __shfl_xor_sync(0xffffffffu, s4.w, o);
        }
        float4 rs4;
        rs4.x = 1.0f / (s4.x + 1e-16f);
        rs4.y = 1.0f / (s4.y + 1e-16f);
        rs4.z = 1.0f / (s4.z + 1e-16f);
        rs4.w = 1.0f / (s4.w + 1e-16f);
        const float rs_m = (hh == 0) ? rs4.x : (hh == 1) ? rs4.y : (hh == 2) ? rs4.z : rs4.w;
        __syncwarp();

        float4 acc = {0.f, 0.f, 0.f, 0.f};
        #pragma unroll 2
        for (int k = 0; k < E1; ++k) {
            const int src = src8[sb + k];
            const float e = mybuf[k * 4 + hh];
            const float4 v = xls4[src * 33 + l];
            acc.x += e * v.x; acc.y += e * v.y; acc.z += e * v.z; acc.w += e * v.w;
        }
        float4 gout;
        gout.x = acc.x * rs_m + bias4.x;
        gout.y = acc.y * rs_m + bias4.y;
        gout.z = acc.z * rs_m + bias4.z;
        gout.w = acc.w * rs_m + bias4.w;
        gout.x = (gout.x > 0.f) ? gout.x : (__expf(gout.x) - 1.f);
        gout.y = (gout.y > 0.f) ? gout.y : (__expf(gout.y) - 1.f);
        gout.z = (gout.z > 0.f) ? gout.z : (__expf(gout.z) - 1.f);
        gout.w = (gout.w > 0.f) ? gout.w : (__expf(gout.w) - 1.f);
        float4 hv = ((const float4*)(h + node * HID))[l];
        hv.x += gout.x; hv.y += gout.y; hv.z += gout.z; hv.w += gout.w;
        float sum = hv.x + hv.y + hv.z + hv.w;
        float sq  = hv.x*hv.x + hv.y*hv.y + hv.z*hv.z + hv.w*hv.w;
        #pragma unroll
        for (int o = 16; o; o >>= 1) {
            sum += __shfl_xor_sync(0xffffffffu, sum, o);
            sq  += __shfl_xor_sync(0xffffffffu, sq, o);
        }
        const float mu = sum * (1.0f / 128.0f);
        const float var = sq * (1.0f / 128.0f) - mu * mu;
        const float inv = rsqrtf(var + 1e-5f);
        float4 ho;
        ho.x = (hv.x - mu) * inv * g4v.x + b4v.x;
        ho.y = (hv.y - mu) * inv * g4v.y + b4v.y;
        ho.z = (hv.z - mu) * inv * g4v.z + b4v.z;
        ho.w = (hv.w - mu) * inv * g4v.w + b4v.w;
        ((float4*)(h + node * HID))[l] = ho;

        if (attn_out) {
            float* row = attnrow + w * 128;
            ((float4*)row)[l] = make_float4(0.f, 0.f, 0.f, 0.f);
            __syncwarp();
            for (int k = l; k < E1; k += 32) {
                const float4 e4 = ((float4*)mybuf)[k];
                const float val = 0.25f * (e4.x * rs4.x + e4.y * rs4.y +
                                           e4.z * rs4.z + e4.w * rs4.w);
                atomicAdd(&row[src8[sb + k]], val);
            }
            __syncwarp();
            ((float4*)(attn_out + (size_t)b * CNODE * CNODE + (size_t)d * CNODE))[l] =
                ((float4*)row)[l];
            __syncwarp();
        }
    }
}

// ---------------- launch ----------------
extern "C" void kernel_launch(void* const* d_in, const int* in_sizes, int n_in,
                              void* d_out, int out_size) {
    const float* x        = (const float*)d_in[0];
    const void*  ei       = d_in[1];
    const float* emb_W    = (const float*)d_in[2];
    const float* emb_b    = (const float*)d_in[3];
    const float* lin_l_W  = (const float*)d_in[4];
    const float* lin_l_b  = (const float*)d_in[5];
    const float* lin_r_W  = (const float*)d_in[6];
    const float* lin_r_b  = (const float*)d_in[7];
    const float* att      = (const float*)d_in[8];
    const float* gat_bias = (const float*)d_in[9];
    const float* ln_g     = (const float*)d_in[10];
    const float* ln_b     = (const float*)d_in[11];
    const float* proj_W   = (const float*)d_in[12];
    const float* proj_b   = (const float*)d_in[13];
    float* out = (float*)d_out;

    float *h, *xl, *xr;
    cudaGetSymbolAddress((void**)&h,  g_h);
    cudaGetSymbolAddress((void**)&xl, g_xl);
    cudaGetSymbolAddress((void**)&xr, g_xr);

    cudaFuncSetAttribute(gat_kernel, cudaFuncAttributeMaxDynamicSharedMemorySize, GAT_SMEM_BYTES);

    build_csr_kernel<<<1, 256>>>(ei);

    // embed (fused input transpose): h = xT @ emb_W + emb_b
    gemm_kernel<<<dim3(1, NNODE / 64), 256>>>(x, 0, emb_W, HID, emb_b, h, HID, LSEQ, 1);

    for (int layer = 0; layer < 2; ++layer) {
        gemm_kernel<<<dim3(1, NNODE / 64), 256>>>(h, HID, lin_l_W + layer * HID * HID, HID,
                                                  lin_l_b + layer * HID, xl, HID, HID, 0);
        gemm_kernel<<<dim3(1, NNODE / 64), 256>>>(h, HID, lin_r_W + layer * HID * HID, HID,
                                                  lin_r_b + layer * HID, xr, HID, HID, 0);
        float* attn_ptr = (layer == 1 && out_size >= OUT_ELEMS + ATTN_ELEMS) ? out + OUT_ELEMS : nullptr;
        gat_kernel<<<BATCH, 512, GAT_SMEM_BYTES>>>(h, xl, xr,
                                                   att + layer * HID, gat_bias + layer * HID,
                                                   ln_g + layer * HID, ln_b + layer * HID, attn_ptr);
    }

    // proj (fused output transpose): out = (h @ proj_W + proj_b) reshaped/transposed
    gemm_kernel<<<dim3(LSEQ / 128, NNODE / 64), 256>>>(h, HID, proj_W, LSEQ, proj_b, out, 0, HID, 2);
}

// round 6
// speedup vs baseline: 1.6206x; 1.6206x over previous
#include <cuda_runtime.h>
#include <cuda_bf16.h>
#include <cstdint>

// ---------------- problem constants ----------------
#define BATCH 256
#define LSEQ  256
#define CNODE 128
#define HID   128
#define NHEAD 4
#define DHEAD 32
#define NEDGE 4096
#define NSLOT (NEDGE + CNODE)               // 4224 incl. self loops
#define NNODE (BATCH * CNODE)               // 32768
#define OUT_ELEMS  (BATCH * LSEQ * CNODE)   // 8388608
#define ATTN_ELEMS (BATCH * CNODE * CNODE)  // 4194304

// ---------------- scratch ----------------
__device__ float g_h[NNODE * HID];         // 16 MB  node features
__device__ float g_xl[NNODE * HID];        // 16 MB
__device__ float g_xr[NNODE * HID];        // 16 MB
__device__ int   g_slot_ptr[CNODE + 1];    // slot CSR (self-loop first per dst)
__device__ int   g_slot_src[NSLOT];

// packed f32x2 FMA (ptxas never auto-fuses; must come from PTX)
#define FMA2(d, a, b, c) \
    asm("fma.rn.f32x2 %0, %1, %2, %3;" : "=l"(d) : "l"(a), "l"(b), "l"(c))

__device__ __forceinline__ void cp_async16(void* smem_dst, const void* gptr) {
    uint32_t sa = (uint32_t)__cvta_generic_to_shared(smem_dst);
    asm volatile("cp.async.cg.shared.global [%0], [%1], 16;" :: "r"(sa), "l"(gptr));
}
#define CP_COMMIT() asm volatile("cp.async.commit_group;")
#define CP_WAIT0()  asm volatile("cp.async.wait_group 0;")

// ---------------- CSR/slot build ----------------
__global__ void build_csr_kernel(const void* __restrict__ eiraw) {
    __shared__ int cnt[CNODE];
    __shared__ int base[CNODE + 1];
    __shared__ int is64_s;
    const long long* e64 = (const long long*)eiraw;
    const int* e32 = (const int*)eiraw;
    int tid = threadIdx.x;

    if (tid == 0) is64_s = 1;
    if (tid < CNODE) cnt[tid] = 0;
    __syncthreads();
    int bad = 0;
    for (int i = tid; i < NEDGE; i += 256) {
        long long v = e64[i];
        if (v < 0 || v >= CNODE) bad = 1;
    }
    if (bad) is64_s = 0;
    __syncthreads();
    const int is64 = is64_s;

    for (int e = tid; e < NEDGE; e += 256) {
        int d = is64 ? (int)e64[NEDGE + e] : e32[NEDGE + e];
        atomicAdd(&cnt[d], 1);
    }
    __syncthreads();
    if (tid == 0) {
        int run = 0;
        for (int i = 0; i < CNODE; ++i) { base[i] = run; run += cnt[i]; }
        base[CNODE] = run;
    }
    __syncthreads();
    if (tid <= CNODE) g_slot_ptr[tid] = base[tid] + tid;
    if (tid < CNODE) {
        g_slot_src[base[tid] + tid] = tid;   // self loop first
        cnt[tid] = base[tid];
    }
    __syncthreads();
    for (int e = tid; e < NEDGE; e += 256) {
        int d = is64 ? (int)e64[NEDGE + e] : e32[NEDGE + e];
        int s = is64 ? (int)e64[e]         : e32[e];
        int pos = atomicAdd(&cnt[d], 1);
        g_slot_src[pos + d + 1] = s;
    }
}

// ---------------- fused GEMM (templated mode, cp.async A, reg-prefetch B) ----
// C(MxN-tile 64x128) = A(MxK) @ W(KxN) + bias; double-buffered, one sync/chunk.
// MODE 0: A row-major (lda), C row-major (ldc)
// MODE 1: A[m][k] = x[m>>7][k][m&127]  (fused input transpose, register staging)
// MODE 2: like 0 for A; C written as out[b][l][c] (fused output transpose)
#define AST 36                      // A_s row stride (floats): 144 B, 16B-aligned
template <int MODE>
__global__ __launch_bounds__(256, 2) void gemm_t(
    const float* __restrict__ A, int lda,
    const float* __restrict__ W, int ldb,
    const float* __restrict__ bias,
    float* __restrict__ C, int ldc, int K)
{
    __shared__ __align__(16) float smem_all[12800];   // 50 KB
    float* const As0 = smem_all;
    float* const As1 = smem_all + 2304;
    float* const Bs0 = smem_all + 4608;               // pair-major: [16kp][128n][2]
    float* const Bs1 = smem_all + 8704;

    const int tid = threadIdx.x;
    const int tx = tid & 31, ty = tid >> 5;
    const int m0 = blockIdx.y * 64;
    const int n0 = blockIdx.x * 128;

    unsigned long long acc[8][4];
    #pragma unroll
    for (int i = 0; i < 8; ++i)
        #pragma unroll
        for (int j = 0; j < 4; ++j) acc[i][j] = 0ull;

    const int nc = K >> 5;
    float4 aR[2];                                     // MODE 1 only
    float4 bR[4];

    // ---- prologue: chunk 0 ----
    if (MODE == 1) {
        const float* xb = A + (size_t)(m0 >> 7) * (LSEQ * CNODE) + (m0 & 127);
        #pragma unroll
        for (int r = 0; r < 2; ++r) {
            int f4 = tid + r * 256;
            int kk = f4 >> 4, mq = f4 & 15;
            aR[r] = *(const float4*)(xb + (size_t)kk * CNODE + mq * 4);
        }
    } else {
        #pragma unroll
        for (int r = 0; r < 2; ++r) {
            int f4 = tid + r * 256;
            int m = f4 >> 3, kq = f4 & 7;
            cp_async16(As0 + m * AST + kq * 4, A + (size_t)(m0 + m) * lda + kq * 4);
        }
        CP_COMMIT();
    }
    #pragma unroll
    for (int r = 0; r < 4; ++r) {
        int f4 = tid + r * 256;
        int kk = f4 >> 5, nq = f4 & 31;
        bR[r] = *(const float4*)(W + (size_t)kk * ldb + n0 + nq * 4);
    }

    for (int c = 0; c < nc; ++c) {
        float* Ab = (c & 1) ? As1 : As0;
        float* Bb = (c & 1) ? Bs1 : Bs0;
        // ---- STS current B (and A for MODE 1) ----
        #pragma unroll
        for (int r = 0; r < 4; ++r) {
            int f4 = tid + r * 256;
            int kk = f4 >> 5, nq = f4 & 31;
            float* p = Bb + (kk >> 1) * 256 + (kk & 1);
            p[(nq * 4 + 0) * 2] = bR[r].x;
            p[(nq * 4 + 1) * 2] = bR[r].y;
            p[(nq * 4 + 2) * 2] = bR[r].z;
            p[(nq * 4 + 3) * 2] = bR[r].w;
        }
        if (MODE == 1) {
            #pragma unroll
            for (int r = 0; r < 2; ++r) {
                int f4 = tid + r * 256;
                int kk = f4 >> 4, mq = f4 & 15;
                float* p = Ab + kk;
                p[(mq * 4 + 0) * AST] = aR[r].x;
                p[(mq * 4 + 1) * AST] = aR[r].y;
                p[(mq * 4 + 2) * AST] = aR[r].z;
                p[(mq * 4 + 3) * AST] = aR[r].w;
            }
        }
        if (MODE != 1) CP_WAIT0();
        __syncthreads();
        // ---- issue next chunk's loads (overlap with compute) ----
        if (c + 1 < nc) {
            const int k0 = (c + 1) << 5;
            float* An = (c & 1) ? As0 : As1;
            if (MODE == 1) {
                const float* xb = A + (size_t)(m0 >> 7) * (LSEQ * CNODE) + (m0 & 127);
                #pragma unroll
                for (int r = 0; r < 2; ++r) {
                    int f4 = tid + r * 256;
                    int kk = f4 >> 4, mq = f4 & 15;
                    aR[r] = *(const float4*)(xb + (size_t)(k0 + kk) * CNODE + mq * 4);
                }
            } else {
                #pragma unroll
                for (int r = 0; r < 2; ++r) {
                    int f4 = tid + r * 256;
                    int m = f4 >> 3, kq = f4 & 7;
                    cp_async16(An + m * AST + kq * 4,
                               A + (size_t)(m0 + m) * lda + k0 + kq * 4);
                }
                CP_COMMIT();
            }
            #pragma unroll
            for (int r = 0; r < 4; ++r) {
                int f4 = tid + r * 256;
                int kk = f4 >> 5, nq = f4 & 31;
                bR[r] = *(const float4*)(W + (size_t)(k0 + kk) * ldb + n0 + nq * 4);
            }
        }
        // ---- compute ----
        #pragma unroll
        for (int kp = 0; kp < 16; ++kp) {
            unsigned long long b2[4];
            #pragma unroll
            for (int j = 0; j < 4; ++j)
                b2[j] = *(const unsigned long long*)(Bb + kp * 256 + (tx + j * 32) * 2);
            #pragma unroll
            for (int i = 0; i < 8; ++i) {
                unsigned long long a2 = *(const unsigned long long*)(Ab + (ty * 8 + i) * AST + kp * 2);
                #pragma unroll
                for (int j = 0; j < 4; ++j)
                    FMA2(acc[i][j], a2, b2[j], acc[i][j]);
            }
        }
    }

    if (MODE != 2) {
        #pragma unroll
        for (int i = 0; i < 8; ++i) {
            int m = m0 + ty * 8 + i;
            #pragma unroll
            for (int j = 0; j < 4; ++j) {
                int n = n0 + tx + j * 32;
                float2 p = *(float2*)&acc[i][j];
                C[(size_t)m * ldc + n] = p.x + p.y + bias[n];
            }
        }
    } else {
        __syncthreads();                              // everyone done reading smem
        float* Cs = smem_all;                         // [64 c][128 l] stride 129
        #pragma unroll
        for (int i = 0; i < 8; ++i) {
            #pragma unroll
            for (int j = 0; j < 4; ++j) {
                int n = tx + j * 32;
                float2 p = *(float2*)&acc[i][j];
                Cs[(ty * 8 + i) * 129 + n] = p.x + p.y + bias[n0 + n];
            }
        }
        __syncthreads();
        const int b = m0 >> 7, c0 = m0 & 127;
        float* ob = C + (size_t)b * (LSEQ * CNODE) + c0;
        #pragma unroll
        for (int rep = 0; rep < 8; ++rep) {
            int l = rep * 16 + (tid >> 4);
            int ci = (tid & 15) * 4;
            float4 v;
            v.x = Cs[(ci + 0) * 129 + l];
            v.y = Cs[(ci + 1) * 129 + l];
            v.z = Cs[(ci + 2) * 129 + l];
            v.w = Cs[(ci + 3) * 129 + l];
            *(float4*)(ob + (size_t)(n0 + l) * CNODE + ci) = v;
        }
    }
}

// ---------------- GAT layer kernel (warp-per-dst, all warp-local) ----------------
#define XL_F     (CNODE * 132)                 // 16896
#define LBUF_F   (16 * 128 * 4)                // 8192
#define ATTN_F   (16 * 128)                    // 2048
#define A_F      128
#define SMEM_F   (XL_F + LBUF_F + ATTN_F + A_F)
#define SRC_B_OFF (SMEM_F * 4)
#define PTR_B_OFF (SRC_B_OFF + NSLOT)
#define GAT_SMEM_BYTES (PTR_B_OFF + (CNODE + 1) * 4)

__global__ __launch_bounds__(512, 2) void gat_kernel(
    float* __restrict__ h, const float* __restrict__ xl, const float* __restrict__ xr,
    const float* __restrict__ att, const float* __restrict__ gat_bias,
    const float* __restrict__ ln_g, const float* __restrict__ ln_b,
    float* __restrict__ attn_out)
{
    extern __shared__ __align__(16) float sm[];
    float* xl_s   = sm;
    float* lbuf   = sm + XL_F;
    float* attnrow= sm + XL_F + LBUF_F;
    float* a_s    = sm + XL_F + LBUF_F + ATTN_F;
    unsigned char* src8 = (unsigned char*)sm + SRC_B_OFF;
    int* ptr_s = (int*)((char*)sm + PTR_B_OFF);

    const int b = blockIdx.x;
    const int tid = threadIdx.x;
    const int w = tid >> 5;
    const int l = tid & 31;
    const int hh = l >> 3;

    {
        const float4* src4 = (const float4*)(xl + (size_t)b * CNODE * HID);
        for (int i = tid; i < CNODE * 32; i += 512) {
            int node = i >> 5, d4 = i & 31;
            ((float4*)xl_s)[node * 33 + d4] = src4[i];
        }
        for (int i = tid; i < NSLOT; i += 512) src8[i] = (unsigned char)g_slot_src[i];
        if (tid <= CNODE) ptr_s[tid] = g_slot_ptr[tid];
        if (tid < 128) a_s[tid] = att[tid];
    }
    __syncthreads();

    const float4 a4 = ((const float4*)a_s)[l];
    const float4 bias4 = ((const float4*)gat_bias)[l];
    const float4 g4v = ((const float4*)ln_g)[l];
    const float4 b4v = ((const float4*)ln_b)[l];
    float* mybuf = lbuf + w * 512;
    const float4* xls4 = (const float4*)xl_s;

    for (int d = w; d < CNODE; d += 16) {
        const int sb = ptr_s[d];
        int E1 = ptr_s[d + 1] - sb;
        if (E1 > 128) E1 = 128;
        const size_t node = (size_t)b * CNODE + d;
        const float4 xr4 = ((const float4*)(xr + node * HID))[l];

        float m = -1e30f;
        #pragma unroll 2
        for (int k = 0; k < E1; ++k) {
            const int src = src8[sb + k];
            const float4 v = xls4[src * 33 + l];
            float p;
            {
                float t0 = v.x + xr4.x; t0 = fmaxf(t0, 0.2f * t0);
                float t1 = v.y + xr4.y; t1 = fmaxf(t1, 0.2f * t1);
                float t2 = v.z + xr4.z; t2 = fmaxf(t2, 0.2f * t2);
                float t3 = v.w + xr4.w; t3 = fmaxf(t3, 0.2f * t3);
                p = t0 * a4.x + t1 * a4.y + t2 * a4.z + t3 * a4.w;
            }
            p += __shfl_xor_sync(0xffffffffu, p, 4);
            p += __shfl_xor_sync(0xffffffffu, p, 2);
            p += __shfl_xor_sync(0xffffffffu, p, 1);
            if ((l & 7) == 0) mybuf[k * 4 + hh] = p;
            m = fmaxf(m, p);
        }
        __syncwarp();
        float4 m4;
        m4.x = __shfl_sync(0xffffffffu, m, 0);
        m4.y = __shfl_sync(0xffffffffu, m, 8);
        m4.z = __shfl_sync(0xffffffffu, m, 16);
        m4.w = __shfl_sync(0xffffffffu, m, 24);

        float4 s4 = {0.f, 0.f, 0.f, 0.f};
        for (int k = l; k < E1; k += 32) {
            float4 f = ((float4*)mybuf)[k];
            f.x = __expf(f.x - m4.x);
            f.y = __expf(f.y - m4.y);
            f.z = __expf(f.z - m4.z);
            f.w = __expf(f.w - m4.w);
            ((float4*)mybuf)[k] = f;
            s4.x += f.x; s4.y += f.y; s4.z += f.z; s4.w += f.w;
        }
        #pragma unroll
        for (int o = 16; o; o >>= 1) {
            s4.x += __shfl_xor_sync(0xffffffffu, s4.x, o);
            s4.y += __shfl_xor_sync(0xffffffffu, s4.y, o);
            s4.z += __shfl_xor_sync(0xffffffffu, s4.z, o);
            s4.w += __shfl_xor_sync(0xffffffffu, s4.w, o);
        }
        float4 rs4;
        rs4.x = 1.0f / (s4.x + 1e-16f);
        rs4.y = 1.0f / (s4.y + 1e-16f);
        rs4.z = 1.0f / (s4.z + 1e-16f);
        rs4.w = 1.0f / (s4.w + 1e-16f);
        const float rs_m = (hh == 0) ? rs4.x : (hh == 1) ? rs4.y : (hh == 2) ? rs4.z : rs4.w;
        __syncwarp();

        float4 acc = {0.f, 0.f, 0.f, 0.f};
        #pragma unroll 2
        for (int k = 0; k < E1; ++k) {
            const int src = src8[sb + k];
            const float e = mybuf[k * 4 + hh];
            const float4 v = xls4[src * 33 + l];
            acc.x += e * v.x; acc.y += e * v.y; acc.z += e * v.z; acc.w += e * v.w;
        }
        float4 gout;
        gout.x = acc.x * rs_m + bias4.x;
        gout.y = acc.y * rs_m + bias4.y;
        gout.z = acc.z * rs_m + bias4.z;
        gout.w = acc.w * rs_m + bias4.w;
        gout.x = (gout.x > 0.f) ? gout.x : (__expf(gout.x) - 1.f);
        gout.y = (gout.y > 0.f) ? gout.y : (__expf(gout.y) - 1.f);
        gout.z = (gout.z > 0.f) ? gout.z : (__expf(gout.z) - 1.f);
        gout.w = (gout.w > 0.f) ? gout.w : (__expf(gout.w) - 1.f);
        float4 hv = ((const float4*)(h + node * HID))[l];
        hv.x += gout.x; hv.y += gout.y; hv.z += gout.z; hv.w += gout.w;
        float sum = hv.x + hv.y + hv.z + hv.w;
        float sq  = hv.x*hv.x + hv.y*hv.y + hv.z*hv.z + hv.w*hv.w;
        #pragma unroll
        for (int o = 16; o; o >>= 1) {
            sum += __shfl_xor_sync(0xffffffffu, sum, o);
            sq  += __shfl_xor_sync(0xffffffffu, sq, o);
        }
        const float mu = sum * (1.0f / 128.0f);
        const float var = sq * (1.0f / 128.0f) - mu * mu;
        const float inv = rsqrtf(var + 1e-5f);
        float4 ho;
        ho.x = (hv.x - mu) * inv * g4v.x + b4v.x;
        ho.y = (hv.y - mu) * inv * g4v.y + b4v.y;
        ho.z = (hv.z - mu) * inv * g4v.z + b4v.z;
        ho.w = (hv.w - mu) * inv * g4v.w + b4v.w;
        ((float4*)(h + node * HID))[l] = ho;

        if (attn_out) {
            float* row = attnrow + w * 128;
            ((float4*)row)[l] = make_float4(0.f, 0.f, 0.f, 0.f);
            __syncwarp();
            for (int k = l; k < E1; k += 32) {
                const float4 e4 = ((float4*)mybuf)[k];
                const float val = 0.25f * (e4.x * rs4.x + e4.y * rs4.y +
                                           e4.z * rs4.z + e4.w * rs4.w);
                atomicAdd(&row[src8[sb + k]], val);
            }
            __syncwarp();
            ((float4*)(attn_out + (size_t)b * CNODE * CNODE + (size_t)d * CNODE))[l] =
                ((float4*)row)[l];
            __syncwarp();
        }
    }
}

// ---------------- launch ----------------
extern "C" void kernel_launch(void* const* d_in, const int* in_sizes, int n_in,
                              void* d_out, int out_size) {
    const float* x        = (const float*)d_in[0];
    const void*  ei       = d_in[1];
    const float* emb_W    = (const float*)d_in[2];
    const float* emb_b    = (const float*)d_in[3];
    const float* lin_l_W  = (const float*)d_in[4];
    const float* lin_l_b  = (const float*)d_in[5];
    const float* lin_r_W  = (const float*)d_in[6];
    const float* lin_r_b  = (const float*)d_in[7];
    const float* att      = (const float*)d_in[8];
    const float* gat_bias = (const float*)d_in[9];
    const float* ln_g     = (const float*)d_in[10];
    const float* ln_b     = (const float*)d_in[11];
    const float* proj_W   = (const float*)d_in[12];
    const float* proj_b   = (const float*)d_in[13];
    float* out = (float*)d_out;

    float *h, *xl, *xr;
    cudaGetSymbolAddress((void**)&h,  g_h);
    cudaGetSymbolAddress((void**)&xl, g_xl);
    cudaGetSymbolAddress((void**)&xr, g_xr);

    cudaFuncSetAttribute(gat_kernel, cudaFuncAttributeMaxDynamicSharedMemorySize, GAT_SMEM_BYTES);

    build_csr_kernel<<<1, 256>>>(ei);

    // embed (fused input transpose): h = xT @ emb_W + emb_b
    gemm_t<1><<<dim3(1, NNODE / 64), 256>>>(x, 0, emb_W, HID, emb_b, h, HID, LSEQ);

    for (int layer = 0; layer < 2; ++layer) {
        gemm_t<0><<<dim3(1, NNODE / 64), 256>>>(h, HID, lin_l_W + layer * HID * HID, HID,
                                                lin_l_b + layer * HID, xl, HID, HID);
        gemm_t<0><<<dim3(1, NNODE / 64), 256>>>(h, HID, lin_r_W + layer * HID * HID, HID,
                                                lin_r_b + layer * HID, xr, HID, HID);
        float* attn_ptr = (layer == 1 && out_size >= OUT_ELEMS + ATTN_ELEMS) ? out + OUT_ELEMS : nullptr;
        gat_kernel<<<BATCH, 512, GAT_SMEM_BYTES>>>(h, xl, xr,
                                                   att + layer * HID, gat_bias + layer * HID,
                                                   ln_g + layer * HID, ln_b + layer * HID, attn_ptr);
    }

    // proj (fused output transpose): out = (h @ proj_W + proj_b) transposed
    gemm_t<2><<<dim3(LSEQ / 128, NNODE / 64), 256>>>(h, HID, proj_W, LSEQ, proj_b, out, 0, HID);
}